// round 2
// baseline (speedup 1.0000x reference)
#include <cuda_runtime.h>

#define BB 16
#define QL 32
#define TN 10
#define AL 10
#define EE 300
#define EP 301
#define HH 256
#define NEGV -10000000000.0f

// ---- shared memory layout (floats) ----
#define OFF_W     0              // sim_w split: w1,w2,w3 (3*300 = 900)
#define OFF_QE    900            // q_emb [QL][EP]  = 9632
#define OFF_AE    10532          // a_emb [AL][EP]  = 3010 (+2 pad -> 3012)
#define OFF_ENCT  13544          // encT  [600][12] = 7200  (16B aligned: 13544*4 % 16 == 0)
#define OFF_ATT   20744          // atten [AL][QL]  = 320
#define OFF_ATTS  21064          // atten softmax   = 320
#define OFF_QW2   21384          // qW2 [QL] = 32
#define OFF_QM    21416          // q mask [QL] = 32
#define OFF_AW1   21448          // aW1 [AL] (+pad) = 16
#define OFF_AM    21464          // a mask [AL] (+pad) = 16
#define OFF_PART  21480          // partial [HH][AL] = 2560
#define OFF_RED   24040          // reduction buf = 16
#define SMEM_FLOATS 24056
#define SMEM_BYTES (SMEM_FLOATS * 4)

__device__ float g_max_atten[BB * TN * QL];
__device__ float g_alia_score[BB * TN];

__global__ void __launch_bounds__(512, 2)
topic_kernelA(const int* __restrict__ q, const int* __restrict__ alia,
              const float* __restrict__ emb, const float* __restrict__ sim_w,
              const float* __restrict__ sim_b, const float* __restrict__ enc_w,
              const float* __restrict__ enc_b, const float* __restrict__ qlin_w,
              const float* __restrict__ qlin_b)
{
    extern __shared__ float sm[];
    float* w1      = sm + OFF_W;
    float* w2      = w1 + EE;
    float* w3      = w2 + EE;
    float* q_emb   = sm + OFF_QE;
    float* a_emb   = sm + OFF_AE;
    float* encT    = sm + OFF_ENCT;
    float* atten   = sm + OFF_ATT;
    float* attensm = sm + OFF_ATTS;
    float* qW2     = sm + OFF_QW2;
    float* qmaskS  = sm + OFF_QM;
    float* aW1     = sm + OFF_AW1;
    float* amaskS  = sm + OFF_AM;
    float* partial = sm + OFF_PART;
    float* red     = sm + OFF_RED;

    const int tid  = threadIdx.x;
    const int lane = tid & 31;
    const int wid  = tid >> 5;          // 0..15
    const int b    = blockIdx.x / TN;
    const int t    = blockIdx.x % TN;

    const float simb = sim_b[0];

    // ---- load sim_w into smem ----
    for (int i = tid; i < 3 * EE; i += 512) sm[OFF_W + i] = sim_w[i];
    __syncthreads();

    // ---- gather + normalize q rows (warp per row) + qW2 dot ----
    for (int j = wid; j < QL; j += 16) {
        int idx = q[b * QL + j];
        float x[10];
        float ss = 0.f;
        #pragma unroll
        for (int i = 0; i < 10; i++) {
            int e = lane + 32 * i;
            float v = (e < EE) ? emb[(size_t)idx * EE + e] : 0.f;
            x[i] = v;
            ss += v * v;
        }
        #pragma unroll
        for (int o = 16; o; o >>= 1) ss += __shfl_xor_sync(0xffffffffu, ss, o);
        float scale = (idx == 0) ? 0.f : 1.f / fmaxf(sqrtf(ss), 1e-12f);
        float dot = 0.f;
        #pragma unroll
        for (int i = 0; i < 10; i++) {
            int e = lane + 32 * i;
            if (e < EE) {
                float v = x[i] * scale;
                q_emb[j * EP + e] = v;
                dot += v * w2[e];
            }
        }
        #pragma unroll
        for (int o = 16; o; o >>= 1) dot += __shfl_xor_sync(0xffffffffu, dot, o);
        if (lane == 0) {
            qW2[j]    = dot;
            qmaskS[j] = (idx != 0) ? 1.f : 0.f;
        }
    }

    // ---- gather + normalize alias rows (warps 0..9) + aW1 dot ----
    if (wid < AL) {
        int a = wid;
        int idx = alia[(b * TN + t) * AL + a];
        float x[10];
        float ss = 0.f;
        #pragma unroll
        for (int i = 0; i < 10; i++) {
            int e = lane + 32 * i;
            float v = (e < EE) ? emb[(size_t)idx * EE + e] : 0.f;
            x[i] = v;
            ss += v * v;
        }
        #pragma unroll
        for (int o = 16; o; o >>= 1) ss += __shfl_xor_sync(0xffffffffu, ss, o);
        float scale = (idx == 0) ? 0.f : 1.f / fmaxf(sqrtf(ss), 1e-12f);
        float dot = 0.f;
        #pragma unroll
        for (int i = 0; i < 10; i++) {
            int e = lane + 32 * i;
            if (e < EE) {
                float v = x[i] * scale;
                a_emb[a * EP + e] = v;
                encT[(300 + e) * 12 + a] = v;   // second half of enc_in, transposed
                dot += v * w1[e];
            }
        }
        #pragma unroll
        for (int o = 16; o; o >>= 1) dot += __shfl_xor_sync(0xffffffffu, dot, o);
        if (lane == 0) {
            aW1[a]    = dot;
            amaskS[a] = (idx != 0) ? 1.f : 0.f;
        }
    }
    __syncthreads();

    // ---- attention scores: warp = a, lane = q ----
    if (wid < AL) {
        int a = wid, qi = lane;
        const float* qe = q_emb + qi * EP;
        const float* ae = a_emb + a * EP;
        float d = 0.f;
        for (int e = 0; e < EE; e++) d += ae[e] * w3[e] * qe[e];
        float val = aW1[a] + qW2[qi] + d + simb;
        float m = amaskS[a] * qmaskS[qi];
        atten[a * QL + qi] = m * val + (1.f - m) * NEGV;
    }
    __syncthreads();

    // ---- softmax over q per alias row (warps 0..9), max over a (warp 10) ----
    if (wid < AL) {
        int a = wid;
        float v = atten[a * QL + lane];
        float mx = v;
        #pragma unroll
        for (int o = 16; o; o >>= 1) mx = fmaxf(mx, __shfl_xor_sync(0xffffffffu, mx, o));
        float ex = expf(v - mx);
        float s = ex;
        #pragma unroll
        for (int o = 16; o; o >>= 1) s += __shfl_xor_sync(0xffffffffu, s, o);
        attensm[a * QL + lane] = ex / s;
    }
    if (wid == 10) {
        float mx = atten[lane];
        #pragma unroll
        for (int a = 1; a < AL; a++) mx = fmaxf(mx, atten[a * QL + lane]);
        g_max_atten[(b * TN + t) * QL + lane] = mx;
    }
    __syncthreads();

    // ---- alig[a][e] = sum_q attensm[a][q] * q_emb[q][e]  -> encT rows 0..299 ----
    for (int p = tid; p < AL * EE; p += 512) {
        int a = p / EE, e = p - a * EE;
        const float* as = attensm + a * QL;
        float s = 0.f;
        #pragma unroll
        for (int qi = 0; qi < QL; qi++) s += as[qi] * q_emb[qi * EP + e];
        encT[e * 12 + a] = s;
    }
    __syncthreads();

    // ---- enc GEMM fused with relu + qlin reduction ----
    {
        int h = tid & 255;
        int half = tid >> 8;               // which half of e-dim
        float acc[AL];
        #pragma unroll
        for (int a = 0; a < AL; a++) acc[a] = 0.f;
        const float* W = enc_w + h;
        int e0 = half * 300;
        for (int e = e0; e < e0 + 300; e++) {
            float w = W[(size_t)e * HH];
            const float4* r = reinterpret_cast<const float4*>(encT + e * 12);
            float4 v0 = r[0];
            float4 v1 = r[1];
            float2 v2 = *reinterpret_cast<const float2*>(encT + e * 12 + 8);
            acc[0] += v0.x * w; acc[1] += v0.y * w; acc[2] += v0.z * w; acc[3] += v0.w * w;
            acc[4] += v1.x * w; acc[5] += v1.y * w; acc[6] += v1.z * w; acc[7] += v1.w * w;
            acc[8] += v2.x * w; acc[9] += v2.y * w;
        }
        __syncthreads();
        if (half == 1) {
            #pragma unroll
            for (int a = 0; a < AL; a++) partial[h * AL + a] = acc[a];
        }
        __syncthreads();
        float val = 0.f;
        if (half == 0) {
            float eb = enc_b[h];
            float qw = qlin_w[h];
            float s = 0.f;
            #pragma unroll
            for (int a = 0; a < AL; a++) {
                float encv = acc[a] + partial[h * AL + a] + eb;
                s += fmaxf(encv, 0.f);
            }
            val = s * qw;
        }
        #pragma unroll
        for (int o = 16; o; o >>= 1) val += __shfl_xor_sync(0xffffffffu, val, o);
        if (lane == 0) red[wid] = val;
        __syncthreads();
        if (tid == 0) {
            float s = 0.f;
            #pragma unroll
            for (int i = 0; i < 16; i++) s += red[i];
            g_alia_score[b * TN + t] = s + qlin_b[0];
        }
    }
}

__global__ void topic_kernelB(const float* __restrict__ els, const float* __restrict__ elo,
                              const float* __restrict__ cate, const float* __restrict__ cls_w,
                              const float* __restrict__ cls_b, float* __restrict__ out)
{
    int b = blockIdx.x;
    int lane = threadIdx.x;   // 32 threads

    float c0w = cls_w[0], c1w = cls_w[1], c2w = cls_w[2], c3w = cls_w[3], c4w = cls_w[4];
    float cb = cls_b[0];

    float ml[TN];
    #pragma unroll
    for (int t = 0; t < TN; t++) {
        float eo = elo[b * TN + t];
        float es = els[b * TN + t];
        float ca = cate[(b * TN + t) * 2 + 0];
        float cbv = cate[(b * TN + t) * 2 + 1];
        float as = g_alia_score[b * TN + t];
        float lg = eo * c0w + es * c1w + ca * c2w + cbv * c3w + as * c4w + cb;
        float tm = ((es + eo) != 0.f) ? 1.f : 0.f;
        ml[t] = tm * lg + (1.f - tm) * NEGV;
    }
    if (lane < TN) out[b * TN + lane] = ml[lane];

    // softmax over topics
    float mx = ml[0];
    #pragma unroll
    for (int t = 1; t < TN; t++) mx = fmaxf(mx, ml[t]);
    float p[TN];
    float sum = 0.f;
    #pragma unroll
    for (int t = 0; t < TN; t++) { p[t] = expf(ml[t] - mx); sum += p[t]; }
    float inv = 1.f / sum;

    // weighted max-attention, then softmax over q (lane = q)
    float s = 0.f;
    #pragma unroll
    for (int t = 0; t < TN; t++)
        s += p[t] * inv * g_max_atten[(b * TN + t) * QL + lane];

    float m2 = s;
    #pragma unroll
    for (int o = 16; o; o >>= 1) m2 = fmaxf(m2, __shfl_xor_sync(0xffffffffu, m2, o));
    float ex = expf(s - m2);
    float tot = ex;
    #pragma unroll
    for (int o = 16; o; o >>= 1) tot += __shfl_xor_sync(0xffffffffu, tot, o);
    out[BB * TN + b * QL + lane] = ex / tot;
}

extern "C" void kernel_launch(void* const* d_in, const int* in_sizes, int n_in,
                              void* d_out, int out_size)
{
    const int*   q      = (const int*)  d_in[0];
    const int*   alia   = (const int*)  d_in[1];
    const float* els    = (const float*)d_in[2];
    const float* elo    = (const float*)d_in[3];
    const float* cate   = (const float*)d_in[4];
    const float* emb    = (const float*)d_in[5];
    const float* sim_w  = (const float*)d_in[6];
    const float* sim_b  = (const float*)d_in[7];
    const float* enc_w  = (const float*)d_in[8];
    const float* enc_b  = (const float*)d_in[9];
    const float* qlin_w = (const float*)d_in[10];
    const float* qlin_b = (const float*)d_in[11];
    const float* cls_w  = (const float*)d_in[12];
    const float* cls_b  = (const float*)d_in[13];
    float* out = (float*)d_out;

    cudaFuncSetAttribute(topic_kernelA, cudaFuncAttributeMaxDynamicSharedMemorySize, SMEM_BYTES);

    topic_kernelA<<<BB * TN, 512, SMEM_BYTES>>>(q, alia, emb, sim_w, sim_b,
                                                enc_w, enc_b, qlin_w, qlin_b);
    topic_kernelB<<<BB, 32>>>(els, elo, cate, cls_w, cls_b, out);
}